// round 7
// baseline (speedup 1.0000x reference)
#include <cuda_runtime.h>
#include <math.h>

#define B        512
#define IN       1024
#define NN       4224
#define TOTAL    5248
#define KB       128
#define NBLK     33
#define OUT_N    128

// Scratch (device globals: allocation-free rule)
__device__ float g_pre[(size_t)B * NN];   // preactivations [row][node]
__device__ float g_h[(size_t)B * KB];     // current block outputs [row][t]

// ---------------------------------------------------------------------------
// Tiled fp32 GEMM, packed-f32x2 pipe with ZERO pack movs:
//  - As[k][r] layout is naturally m-pair packed: 16B LDS = 2 u64 = 2 row-pairs
//  - Bs stored DUPLICATED ({v,v}) so b-broadcast pairs load directly as u64
// Inner loop per k: 4x LDS.128 + 16x fma.rn.f32x2 (32 FLOPs / 20 issues).
// Double-buffered smem + register prefetch hides the streaming-W DRAM latency
// (W is read exactly once -> L2 misses on every tile without prefetch).
// C[r][jbase+n] (+)= sum_k A[r][k] * Wsub[n*TOTAL + k]
// BM=128, BN=64, BK=16, 256 threads, 8x4 microtile (4 m-pairs x 4 n).
// ---------------------------------------------------------------------------
#define BM   128
#define BN   64
#define BK   16
#define ASTR 132   // floats per k-row (128 + pad), rows stay 16B aligned
#define BSTR 132   // floats per k-row of duplicated B (2*64 + pad)

__device__ __forceinline__ float2 unpack64(unsigned long long v) {
    float2 r;
    asm("mov.b64 {%0, %1}, %2;" : "=f"(r.x), "=f"(r.y) : "l"(v));
    return r;
}

__global__ void __launch_bounds__(256)
gemm_kernel(const float* __restrict__ Aparam, int lda,
            const float* __restrict__ Wsub,
            int jbase, int kc, int accum, int asel)
{
    __shared__ float As[2][BK * ASTR];
    __shared__ float Bs[2][BK * BSTR];

    const float* A = asel ? g_h : Aparam;

    int m0 = blockIdx.x * BM;
    int n0 = blockIdx.y * BN;
    int tid = threadIdx.x;
    int tx = tid & 15;          // n dir: 4 cols each
    int ty = tid >> 4;          // m dir: 8 rows (4 pairs) each

    int a_r = tid >> 1;           // 0..127
    int a_k = (tid & 1) * 8;      // 0 or 8
    int b_r = tid >> 2;           // 0..63
    int b_k = (tid & 3) * 4;      // 0,4,8,12

    const float* aptr = A + (size_t)(m0 + a_r) * lda + a_k;
    const float* bptr = Wsub + (size_t)(n0 + b_r) * TOTAL + b_k;

    unsigned long long acc2[4][4];
#pragma unroll
    for (int i = 0; i < 4; i++)
#pragma unroll
        for (int j = 0; j < 4; j++) acc2[i][j] = 0ull;

    int T = kc / BK;
    float4 ra0, ra1, rb;

    // Preload tile 0 into regs, stage into buffer 0.
    ra0 = *(const float4*)(aptr + 0);
    ra1 = *(const float4*)(aptr + 4);
    rb  = *(const float4*)(bptr + 0);
    {
        float* as0 = As[0];
        as0[(a_k + 0) * ASTR + a_r] = ra0.x;
        as0[(a_k + 1) * ASTR + a_r] = ra0.y;
        as0[(a_k + 2) * ASTR + a_r] = ra0.z;
        as0[(a_k + 3) * ASTR + a_r] = ra0.w;
        as0[(a_k + 4) * ASTR + a_r] = ra1.x;
        as0[(a_k + 5) * ASTR + a_r] = ra1.y;
        as0[(a_k + 6) * ASTR + a_r] = ra1.z;
        as0[(a_k + 7) * ASTR + a_r] = ra1.w;
        float* bs0 = Bs[0];
        *(float2*)&bs0[(b_k + 0) * BSTR + 2 * b_r] = make_float2(rb.x, rb.x);
        *(float2*)&bs0[(b_k + 1) * BSTR + 2 * b_r] = make_float2(rb.y, rb.y);
        *(float2*)&bs0[(b_k + 2) * BSTR + 2 * b_r] = make_float2(rb.z, rb.z);
        *(float2*)&bs0[(b_k + 3) * BSTR + 2 * b_r] = make_float2(rb.w, rb.w);
    }
    __syncthreads();

    for (int t = 0; t < T; t++) {
        int cur = t & 1;

        if (t + 1 < T) {   // prefetch next tile's gmem while computing
            int kk = (t + 1) * BK;
            ra0 = *(const float4*)(aptr + kk);
            ra1 = *(const float4*)(aptr + kk + 4);
            rb  = *(const float4*)(bptr + kk);
        }

        const float* as = As[cur];
        const float* bs = Bs[cur];
#pragma unroll
        for (int k = 0; k < BK; k++) {
            unsigned long long ap[4], bb[4];
            ulonglong2 t0 = *(const ulonglong2*)&as[k * ASTR + ty * 8];
            ulonglong2 t1 = *(const ulonglong2*)&as[k * ASTR + ty * 8 + 4];
            ap[0] = t0.x; ap[1] = t0.y; ap[2] = t1.x; ap[3] = t1.y;
            ulonglong2 u0 = *(const ulonglong2*)&bs[k * BSTR + tx * 8];
            ulonglong2 u1 = *(const ulonglong2*)&bs[k * BSTR + tx * 8 + 4];
            bb[0] = u0.x; bb[1] = u0.y; bb[2] = u1.x; bb[3] = u1.y;

#pragma unroll
            for (int i = 0; i < 4; i++)
#pragma unroll
                for (int j = 0; j < 4; j++)
                    asm("fma.rn.f32x2 %0, %1, %2, %0;"
                        : "+l"(acc2[i][j]) : "l"(ap[i]), "l"(bb[j]));
        }

        if (t + 1 < T) {
            float* as1 = As[1 - cur];   // other buffer: safe, nobody reads it
            as1[(a_k + 0) * ASTR + a_r] = ra0.x;
            as1[(a_k + 1) * ASTR + a_r] = ra0.y;
            as1[(a_k + 2) * ASTR + a_r] = ra0.z;
            as1[(a_k + 3) * ASTR + a_r] = ra0.w;
            as1[(a_k + 4) * ASTR + a_r] = ra1.x;
            as1[(a_k + 5) * ASTR + a_r] = ra1.y;
            as1[(a_k + 6) * ASTR + a_r] = ra1.z;
            as1[(a_k + 7) * ASTR + a_r] = ra1.w;
            float* bs1 = Bs[1 - cur];
            *(float2*)&bs1[(b_k + 0) * BSTR + 2 * b_r] = make_float2(ra0.x * 0.0f + rb.x, rb.x);
            bs1[(b_k + 0) * BSTR + 2 * b_r]     = rb.x;
            bs1[(b_k + 0) * BSTR + 2 * b_r + 1] = rb.x;
            *(float2*)&bs1[(b_k + 1) * BSTR + 2 * b_r] = make_float2(rb.y, rb.y);
            *(float2*)&bs1[(b_k + 2) * BSTR + 2 * b_r] = make_float2(rb.z, rb.z);
            *(float2*)&bs1[(b_k + 3) * BSTR + 2 * b_r] = make_float2(rb.w, rb.w);
            __syncthreads();
        }
    }

    // Epilogue: pair i = rows (ty*8+2i, ty*8+2i+1), cols tx*4..tx*4+3.
#pragma unroll
    for (int i = 0; i < 4; i++) {
        float2 v[4];
#pragma unroll
        for (int j = 0; j < 4; j++) v[j] = unpack64(acc2[i][j]);

        float4* c0 = (float4*)(g_pre + (size_t)(m0 + ty * 8 + 2 * i) * NN
                               + jbase + n0 + tx * 4);
        float4* c1 = (float4*)((float*)c0 + NN);
        if (accum) {
            float4 o0 = *c0, o1 = *c1;
            o0.x += v[0].x; o0.y += v[1].x; o0.z += v[2].x; o0.w += v[3].x;
            o1.x += v[0].y; o1.y += v[1].y; o1.z += v[2].y; o1.w += v[3].y;
            *c0 = o0; *c1 = o1;
        } else {
            float4 o0, o1;
            o0.x = v[0].x; o0.y = v[1].x; o0.z = v[2].x; o0.w = v[3].x;
            o1.x = v[0].y; o1.y = v[1].y; o1.z = v[2].y; o1.w = v[3].y;
            *c0 = o0; *c1 = o1;
        }
    }
}

// ---------------------------------------------------------------------------
// In-block sequential recurrence (unchanged from round 6 — validated).
// ---------------------------------------------------------------------------
#define C2LOG2E 2.8853900817779268f

__global__ void __launch_bounds__(512, 1)
seq_kernel(const float* __restrict__ W, float* __restrict__ out, int b)
{
    extern __shared__ float ws[];  // 128*129 floats = 66048 B

    int tid  = threadIdx.x;        // 512
    int lane = tid & 31;
    int row  = blockIdx.x * 16 + (tid >> 5);
    int j0   = b * KB;

    {
        const float* Wt = W + (size_t)j0 * TOTAL + IN + j0;
#pragma unroll
        for (int ii = 0; ii < 32; ii++) {
            int idx = tid + ii * 512;
            int i = idx >> 7;
            int t = idx & 127;
            float v = Wt[(size_t)i * TOTAL + t] * C2LOG2E;
            ws[i * 129 + t] = (t < i) ? v : 0.0f;
        }
    }
    __syncthreads();

    float z[4];
#pragma unroll
    for (int q = 0; q < 4; q++)
        z[q] = g_pre[(size_t)row * NN + j0 + lane + 32 * q] * C2LOG2E;

    const float* wbase = ws + lane * 129;

#pragma unroll
    for (int slot = 0; slot < 4; slot++) {
#pragma unroll
        for (int t2 = 0; t2 < 32; t2++) {
            int t = slot * 32 + t2;

            float e;  asm("ex2.approx.f32 %0, %1;" : "=f"(e) : "f"(z[slot]));
            float d = e + 1.0f;
            float r;  asm("rcp.approx.f32 %0, %1;" : "=f"(r) : "f"(d));
            float hv = fmaf(-2.0f, r, 1.0f);

            float h = __shfl_sync(0xffffffffu, hv, t2);

#pragma unroll
            for (int q = slot; q < 4; q++)
                z[q] = fmaf(h, wbase[q * 32 * 129 + t], z[q]);
        }
    }

    const bool isOut = (b == NBLK - 1);
    if (!isOut) {
        float* ghrow = g_h + (size_t)row * KB;
#pragma unroll
        for (int q = 0; q < 4; q++) {
            float e;  asm("ex2.approx.f32 %0, %1;" : "=f"(e) : "f"(z[q]));
            float d = e + 1.0f;
            float r;  asm("rcp.approx.f32 %0, %1;" : "=f"(r) : "f"(d));
            ghrow[q * 32 + lane] = fmaf(-2.0f, r, 1.0f);
        }
    } else {
        float* orow = out + (size_t)row * OUT_N;
#pragma unroll
        for (int q = 0; q < 4; q++) {
            float e;  asm("ex2.approx.f32 %0, %1;" : "=f"(e) : "f"(z[q]));
            float d = e + 1.0f;
            float r;  asm("rcp.approx.f32 %0, %1;" : "=f"(r) : "f"(d));
            float h = fmaf(-2.0f, r, 1.0f);
            orow[q * 32 + lane] = 1.0f / (1.0f + __expf(-h));
        }
    }
}

// ---------------------------------------------------------------------------
extern "C" void kernel_launch(void* const* d_in, const int* in_sizes, int n_in,
                              void* d_out, int out_size)
{
    const float* x = (const float*)d_in[0];   // [512][1024]
    const float* W = (const float*)d_in[1];   // [4224][5248]
    float* out = (float*)d_out;               // [512][128]

    (void)in_sizes; (void)n_in; (void)out_size;

    cudaFuncSetAttribute(seq_kernel,
                         cudaFuncAttributeMaxDynamicSharedMemorySize, 66048);

    // Phase A: pre = x @ W[:, :1024]^T    (writes all of g_pre)
    gemm_kernel<<<dim3(B / BM, NN / BN), 256>>>(x, IN, W, /*jbase=*/0,
                                                /*kc=*/IN, /*accum=*/0,
                                                /*asel=*/0);

    for (int b = 0; b < NBLK; b++) {
        seq_kernel<<<32, 512, 66048>>>(W, out, b);

        if (b < NBLK - 1) {
            int jbase = (b + 1) * KB;
            int nrem  = NN - jbase;               // multiple of 128
            const float* Wsub = W + (size_t)jbase * TOTAL + (IN + b * KB);
            gemm_kernel<<<dim3(B / BM, nrem / BN), 256>>>(nullptr, KB, Wsub,
                                                          jbase, KB,
                                                          /*accum=*/1,
                                                          /*asel=*/1);
        }
    }
}

// round 8
// speedup vs baseline: 1.4071x; 1.4071x over previous
#include <cuda_runtime.h>
#include <math.h>

#define B        512
#define IN       1024
#define NN       4224
#define TOTAL    5248
#define KB       128
#define NBLK     33
#define OUT_N    128
#define C2LOG2E  2.8853900817779268f

// Device-global scratch (allocation-free rule).
// pre(total) for node column = g_pre (preA + near-updates) + g_upd (far updates).
__device__ float g_pre [(size_t)B * NN];
__device__ float g_upd [(size_t)B * NN];
__device__ float g_hall[(size_t)B * NN];   // h for every node, [row][node]

// ---------------------------------------------------------------------------
// Tiled fp32 GEMM (round-6 validated form: FFMA2 with pack movs, single buf).
// C[r][jbase+n] (+)= sum_k A[r][aoff+k] * Wsub[n*TOTAL + k]
// accum=0 -> C = g_pre (preA chunks); accum=1 -> C = g_upd (far updates).
// asel=0  -> A = Aparam (x);          asel=1  -> A = g_hall.
// BM=128, BN=64, BK=16, 256 threads, 8x4 microtile (4 m-pairs x 4 n).
// ---------------------------------------------------------------------------
#define BM 128
#define BN 64
#define BK 16
#define AS 132
#define BS 68

__global__ void __launch_bounds__(256)
gemm_kernel(const float* __restrict__ Aparam, int lda, int aoff,
            const float* __restrict__ Wsub,
            int jbase, int kc, int accum, int asel)
{
    __shared__ float As_[BK * AS];
    __shared__ float Bs_[BK * BS];

    const float* A = asel ? g_hall : Aparam;
    float*       C = accum ? g_upd : g_pre;

    int m0 = blockIdx.x * BM;
    int n0 = blockIdx.y * BN;
    int tid = threadIdx.x;
    int tx = tid & 15;          // n dir: 4 cols each
    int ty = tid >> 4;          // m dir: 8 rows each

    int a_r = tid >> 1;           // 0..127
    int a_k = (tid & 1) * 8;      // 0 or 8
    int b_r = tid >> 2;           // 0..63
    int b_k = (tid & 3) * 4;      // 0,4,8,12

    unsigned long long acc2[4][4];
#pragma unroll
    for (int i = 0; i < 4; i++)
#pragma unroll
        for (int j = 0; j < 4; j++) acc2[i][j] = 0ull;

    for (int kk = 0; kk < kc; kk += BK) {
        float4 a0 = *(const float4*)(A + (size_t)(m0 + a_r) * lda + aoff + kk + a_k);
        float4 a1 = *(const float4*)(A + (size_t)(m0 + a_r) * lda + aoff + kk + a_k + 4);
        As_[(a_k + 0) * AS + a_r] = a0.x;
        As_[(a_k + 1) * AS + a_r] = a0.y;
        As_[(a_k + 2) * AS + a_r] = a0.z;
        As_[(a_k + 3) * AS + a_r] = a0.w;
        As_[(a_k + 4) * AS + a_r] = a1.x;
        As_[(a_k + 5) * AS + a_r] = a1.y;
        As_[(a_k + 6) * AS + a_r] = a1.z;
        As_[(a_k + 7) * AS + a_r] = a1.w;

        float4 bv = *(const float4*)(Wsub + (size_t)(n0 + b_r) * TOTAL + kk + b_k);
        Bs_[(b_k + 0) * BS + b_r] = bv.x;
        Bs_[(b_k + 1) * BS + b_r] = bv.y;
        Bs_[(b_k + 2) * BS + b_r] = bv.z;
        Bs_[(b_k + 3) * BS + b_r] = bv.w;

        __syncthreads();

#pragma unroll
        for (int k = 0; k < BK; k++) {
            float a[8], b[4];
            *(float4*)&a[0] = *(const float4*)&As_[k * AS + ty * 8];
            *(float4*)&a[4] = *(const float4*)&As_[k * AS + ty * 8 + 4];
            *(float4*)&b[0] = *(const float4*)&Bs_[k * BS + tx * 4];

            unsigned long long ap[4], bb[4];
#pragma unroll
            for (int i = 0; i < 4; i++)
                asm("mov.b64 %0, {%1, %2};"
                    : "=l"(ap[i]) : "f"(a[2 * i]), "f"(a[2 * i + 1]));
#pragma unroll
            for (int j = 0; j < 4; j++)
                asm("mov.b64 %0, {%1, %2};"
                    : "=l"(bb[j]) : "f"(b[j]), "f"(b[j]));

#pragma unroll
            for (int i = 0; i < 4; i++)
#pragma unroll
                for (int j = 0; j < 4; j++)
                    asm("fma.rn.f32x2 %0, %1, %2, %0;"
                        : "+l"(acc2[i][j]) : "l"(ap[i]), "l"(bb[j]));
        }
        __syncthreads();
    }

#pragma unroll
    for (int i = 0; i < 4; i++) {
        float v0[4], v1[4];
#pragma unroll
        for (int j = 0; j < 4; j++)
            asm("mov.b64 {%0, %1}, %2;"
                : "=f"(v0[j]), "=f"(v1[j]) : "l"(acc2[i][j]));

        float* c0 = C + (size_t)(m0 + ty * 8 + 2 * i) * NN + jbase + n0 + tx * 4;
        float* c1 = c0 + NN;
        if (accum) {
#pragma unroll
            for (int j = 0; j < 4; j++) { c0[j] += v0[j]; c1[j] += v1[j]; }
        } else {
            float4 w0, w1;
            w0.x = v0[0]; w0.y = v0[1]; w0.z = v0[2]; w0.w = v0[3];
            w1.x = v1[0]; w1.y = v1[1]; w1.z = v1[2]; w1.w = v1[3];
            *(float4*)c0 = w0;
            *(float4*)c1 = w1;
        }
    }
}

// ---------------------------------------------------------------------------
// Zero g_upd (far-update accumulator). 2112*256 threads * float4 = exact.
// ---------------------------------------------------------------------------
__global__ void zero_upd_kernel()
{
    size_t i = (size_t)blockIdx.x * blockDim.x + threadIdx.x;
    ((float4*)g_upd)[i] = make_float4(0.f, 0.f, 0.f, 0.f);
}

// ---------------------------------------------------------------------------
// In-block sequential recurrence + FUSED near-update of block b+1.
// 32 CTAs x 512 threads, one warp per row; lane owns nodes lane+32q.
// Reads pre = g_pre + g_upd. Publishes h into g_hall (consumed by the far
// update running concurrently on stream s2) and accumulates the rank-128
// near contribution into g_pre[block b+1] (sole writer at this time).
// ---------------------------------------------------------------------------
__global__ void __launch_bounds__(512, 1)
seq_kernel(const float* __restrict__ W, float* __restrict__ out, int b)
{
    extern __shared__ float sm[];
    float* ws = sm;                 // 128*129 floats (weight tile)
    float* hs = sm + 128 * 129;     // 16*128 floats (per-row h staging)

    int tid  = threadIdx.x;         // 512
    int lane = tid & 31;
    int wid  = tid >> 5;            // 0..15
    int row  = blockIdx.x * 16 + wid;
    int j0   = b * KB;

    // Stage this block's triangular tile, pre-scaled; zero t >= i.
    {
        const float* Wt = W + (size_t)j0 * TOTAL + IN + j0;
#pragma unroll
        for (int ii = 0; ii < 32; ii++) {
            int idx = tid + ii * 512;
            int i = idx >> 7;
            int t = idx & 127;
            float v = Wt[(size_t)i * TOTAL + t] * C2LOG2E;
            ws[i * 129 + t] = (t < i) ? v : 0.0f;
        }
    }
    __syncthreads();

    float z[4];
#pragma unroll
    for (int q = 0; q < 4; q++) {
        size_t o = (size_t)row * NN + j0 + lane + 32 * q;
        z[q] = (g_pre[o] + g_upd[o]) * C2LOG2E;
    }

    const float* wbase = ws + lane * 129;

#pragma unroll
    for (int slot = 0; slot < 4; slot++) {
#pragma unroll
        for (int t2 = 0; t2 < 32; t2++) {
            int t = slot * 32 + t2;

            float e;  asm("ex2.approx.f32 %0, %1;" : "=f"(e) : "f"(z[slot]));
            float d = e + 1.0f;
            float r;  asm("rcp.approx.f32 %0, %1;" : "=f"(r) : "f"(d));
            float hv = fmaf(-2.0f, r, 1.0f);

            float h = __shfl_sync(0xffffffffu, hv, t2);

#pragma unroll
            for (int q = slot; q < 4; q++)
                z[q] = fmaf(h, wbase[q * 32 * 129 + t], z[q]);
        }
    }

    // Finalize h for owned nodes.
    float h4[4];
#pragma unroll
    for (int q = 0; q < 4; q++) {
        float e;  asm("ex2.approx.f32 %0, %1;" : "=f"(e) : "f"(z[q]));
        float d = e + 1.0f;
        float r;  asm("rcp.approx.f32 %0, %1;" : "=f"(r) : "f"(d));
        h4[q] = fmaf(-2.0f, r, 1.0f);
    }

    if (b == NBLK - 1) {
        float* orow = out + (size_t)row * OUT_N;
#pragma unroll
        for (int q = 0; q < 4; q++)
            orow[q * 32 + lane] = 1.0f / (1.0f + __expf(-h4[q]));
        return;   // uniform branch per CTA
    }

    // Publish h (global for the far update; smem for the fused near update).
    {
        float* gh = g_hall + (size_t)row * NN + j0;
#pragma unroll
        for (int q = 0; q < 4; q++) {
            gh[q * 32 + lane] = h4[q];
            hs[wid * 128 + q * 32 + lane] = h4[q];
        }
    }
    __syncthreads();   // hs complete; ws reads done -> safe to overwrite ws

    // Stage next block's raw weight tile: ws[t*129 + n] = W[j0+128+n][IN+j0+t]
    {
        const float* Wn = W + (size_t)(j0 + KB) * TOTAL + IN + j0;
#pragma unroll
        for (int ii = 0; ii < 32; ii++) {
            int idx = tid + ii * 512;
            int n = idx >> 7;
            int t = idx & 127;
            ws[t * 129 + n] = Wn[(size_t)n * TOTAL + t];
        }
    }
    __syncthreads();

    // Near update: g_pre[row][block b+1] += h_row @ Wn^T  (warp-local row).
    {
        float acc[4] = {0.f, 0.f, 0.f, 0.f};
        const float* hrow = hs + wid * 128;
#pragma unroll 4
        for (int t = 0; t < 128; t++) {
            float hv = hrow[t];
#pragma unroll
            for (int q = 0; q < 4; q++)
                acc[q] = fmaf(hv, ws[t * 129 + lane + 32 * q], acc[q]);
        }
#pragma unroll
        for (int q = 0; q < 4; q++) {
            size_t o = (size_t)row * NN + j0 + KB + lane + 32 * q;
            g_pre[o] += acc[q];
        }
    }
}

// ---------------------------------------------------------------------------
// Host: pipelined schedule.
//  stream 0 : preA(blocks 0-3), seq(0..32)        [critical path]
//  s2       : zero g_upd, far update(j) j=0..30   [hidden under seq(j+1..)]
//  s3       : preA(blocks 4-11), preA(blocks 12-32) [hidden under early seq]
// seq(b) waits: update(b-2), preA chunk covering blocks b and b+1.
// ---------------------------------------------------------------------------
extern "C" void kernel_launch(void* const* d_in, const int* in_sizes, int n_in,
                              void* d_out, int out_size)
{
    const float* x = (const float*)d_in[0];   // [512][1024]
    const float* W = (const float*)d_in[1];   // [4224][5248]
    float* out = (float*)d_out;               // [512][128]
    (void)in_sizes; (void)n_in; (void)out_size;

    static bool inited = false;
    static cudaStream_t s2, s3;
    static cudaEvent_t evFork, evZ, evC1, evC2;
    static cudaEvent_t evS[NBLK], evU[NBLK];
    if (!inited) {
        cudaStreamCreateWithFlags(&s2, cudaStreamNonBlocking);
        cudaStreamCreateWithFlags(&s3, cudaStreamNonBlocking);
        cudaEventCreateWithFlags(&evFork, cudaEventDisableTiming);
        cudaEventCreateWithFlags(&evZ,    cudaEventDisableTiming);
        cudaEventCreateWithFlags(&evC1,   cudaEventDisableTiming);
        cudaEventCreateWithFlags(&evC2,   cudaEventDisableTiming);
        for (int i = 0; i < NBLK; i++) {
            cudaEventCreateWithFlags(&evS[i], cudaEventDisableTiming);
            cudaEventCreateWithFlags(&evU[i], cudaEventDisableTiming);
        }
        cudaFuncSetAttribute(seq_kernel,
                             cudaFuncAttributeMaxDynamicSharedMemorySize,
                             (128 * 129 + 16 * 128) * 4);
        inited = true;
    }

    // Fork side streams into the capture.
    cudaEventRecord(evFork, 0);
    cudaStreamWaitEvent(s2, evFork, 0);
    cudaStreamWaitEvent(s3, evFork, 0);

    // s2: zero the far-update accumulator.
    zero_upd_kernel<<<2112, 256, 0, s2>>>();
    cudaEventRecord(evZ, s2);

    // s3: preA chunks for blocks 4-11 and 12-32 (hidden under early pipeline).
    gemm_kernel<<<dim3(4, 16), 256, 0, s3>>>(x, IN, 0,
                                             W + (size_t)512 * TOTAL,
                                             512, IN, 0, 0);
    cudaEventRecord(evC1, s3);
    gemm_kernel<<<dim3(4, 42), 256, 0, s3>>>(x, IN, 0,
                                             W + (size_t)1536 * TOTAL,
                                             1536, IN, 0, 0);
    cudaEventRecord(evC2, s3);

    // stream 0: preA chunk for blocks 0-3, then the seq pipeline.
    gemm_kernel<<<dim3(4, 8), 256, 0, 0>>>(x, IN, 0, W, 0, IN, 0, 0);
    cudaStreamWaitEvent(0, evZ, 0);

    for (int b = 0; b < NBLK; b++) {
        if (b >= 2)  cudaStreamWaitEvent(0, evU[b - 2], 0);
        if (b == 3)  cudaStreamWaitEvent(0, evC1, 0);
        if (b == 11) cudaStreamWaitEvent(0, evC2, 0);

        seq_kernel<<<32, 512, (128 * 129 + 16 * 128) * 4, 0>>>(W, out, b);

        if (b <= NBLK - 3) {   // far update: h_b -> blocks b+2..32, on s2
            cudaEventRecord(evS[b], 0);
            cudaStreamWaitEvent(s2, evS[b], 0);
            int jb = (b + 2) * KB;
            gemm_kernel<<<dim3(4, (NN - jb) / 64), 256, 0, s2>>>(
                nullptr, NN, b * KB,
                W + (size_t)jb * TOTAL + IN + b * KB,
                jb, KB, /*accum=*/1, /*asel=*/1);
            cudaEventRecord(evU[b], s2);
        }
    }
}